// round 3
// baseline (speedup 1.0000x reference)
#include <cuda_runtime.h>

// Problem constants
#define B_    32
#define L_    16
#define O_    256
#define DM_   64
#define CELLS 8192      // B*O
#define NROWS 131072    // B*L*O

typedef unsigned long long ull;

// ---------------- packed f32x2 helpers (Blackwell FFMA2 path) ---------------
__device__ __forceinline__ ull packdup(float a) {
    ull d; asm("mov.b64 %0, {%1, %1};" : "=l"(d) : "f"(a)); return d;
}
__device__ __forceinline__ ull pack2(float lo, float hi) {
    ull d; asm("mov.b64 %0, {%1, %2};" : "=l"(d) : "f"(lo), "f"(hi)); return d;
}
__device__ __forceinline__ void unpack2(ull v, float& lo, float& hi) {
    asm("mov.b64 {%0, %1}, %2;" : "=f"(lo), "=f"(hi) : "l"(v));
}
__device__ __forceinline__ ull fma2(ull a, ull b, ull c) {
    ull d; asm("fma.rn.f32x2 %0, %1, %2, %3;" : "=l"(d) : "l"(a), "l"(b), "l"(c)); return d;
}

// ---------------- scratch (__device__ globals: no allocations allowed) ------
__device__ float g_F[(size_t)CELLS * L_ * DM_];   // 8.4M floats: F = X@E, [cell][l][64]
__device__ float g_Wpre[128 * 256];               // [k][n] combined Wi_flow/Wh, gate-interleaved
__device__ float g_GbiasP[O_ * 256];              // per-o gate bias, permuted layout
__device__ float g_part[128 * 128];               // per-CTA LN partials: [cta][sum(64)|sumsq(64)]
__device__ float g_mean[DM_];
__device__ float g_rstd[DM_];
__device__ float g_hlast[(size_t)CELLS * DM_];
__device__ float g_v[(size_t)CELLS * DM_];
__device__ float g_lv[(size_t)CELLS * DM_];

// ---------------- activation helpers ---------------------------------------
__device__ __forceinline__ float sigm_(float x) {
    return 1.0f / (1.0f + __expf(-x));
}
__device__ __forceinline__ float tanh_(float x) {
    float ax = fabsf(x);
    float e  = __expf(-2.0f * ax);
    float t  = (1.0f - e) / (1.0f + e);
    return (x < 0.0f) ? -t : t;
}

// ---------------- prep: softmax(-dis)@E -> Gbias ; weight repack ------------
// blocks 0..255: one per o.  blocks 256..383: Wpre row k = bid-256.
// Gate permutation: column n <-> (dm = n>>2, gate = n&3); gate row g(n) = (n&3)*64 + (n>>2)
__global__ void prep_kernel(const float* __restrict__ dis, const float* __restrict__ E,
                            const float* __restrict__ Wi,  const float* __restrict__ Wh,
                            const float* __restrict__ bi,  const float* __restrict__ bh)
{
    int bid = blockIdx.x, tid = threadIdx.x;
    if (bid < 256) {
        __shared__ float sh[256];   // exp row
        __shared__ float red[256];
        __shared__ float fg[64];    // feat_geo row for this o
        int o = bid;
        float x = -dis[o * 256 + tid];
        red[tid] = x; __syncthreads();
        for (int s = 128; s > 0; s >>= 1) { if (tid < s) red[tid] = fmaxf(red[tid], red[tid + s]); __syncthreads(); }
        float m = red[0];
        __syncthreads();
        float e = __expf(x - m);
        sh[tid] = e;
        red[tid] = e; __syncthreads();
        for (int s = 128; s > 0; s >>= 1) { if (tid < s) red[tid] += red[tid + s]; __syncthreads(); }
        float inv = 1.0f / red[0];
        __syncthreads();
        // fg[e] = inv * sum_k sh[k]*E[k][e]   (4 k-chunks in parallel)
        {
            int ei = tid & 63, ch = tid >> 6;
            float a = 0.0f;
            int k0 = ch * 64;
            for (int k = k0; k < k0 + 64; k++) a = fmaf(sh[k], E[k * 64 + ei], a);
            red[tid] = a;
            __syncthreads();
            if (tid < 64) fg[tid] = (red[tid] + red[64 + tid] + red[128 + tid] + red[192 + tid]) * inv;
            __syncthreads();
        }
        // GbiasP[o][n] = bi[g]+bh[g] + sum_e fg[e]*Wi[g][64+e]
        int n = tid;
        int g = (n & 3) * 64 + (n >> 2);
        float acc = bi[g] + bh[g];
        const float* wrow = Wi + g * 128 + 64;
        #pragma unroll 8
        for (int ei = 0; ei < 64; ei++) acc = fmaf(fg[ei], wrow[ei], acc);
        g_GbiasP[o * 256 + n] = acc;
    } else {
        int k = bid - 256;            // 0..127
        int n = tid;
        int g = (n & 3) * 64 + (n >> 2);
        g_Wpre[k * 256 + n] = (k < 64) ? Wi[g * 128 + k] : Wh[g * 64 + (k - 64)];
    }
}

// ---------------- GEMM1: F = X @ E  (131072x256 @ 256x64) -------------------
// BM=128, N=64 full, E fully resident in SMEM. Thread tile 8x4 (f32x2), 256 threads.
#define G1_SMEM ((256 * 64 + 32 * 132) * 4)
__global__ void __launch_bounds__(256, 2) gemm1_full(const float* __restrict__ X,
                                                     const float* __restrict__ E)
{
    extern __shared__ float sm[];
    float* Es = sm;                 // [256][64]
    float* Xs = sm + 256 * 64;      // [32][132] (k-major, padded)
    const int tid = threadIdx.x;
    const int tx = tid & 15, ty = tid >> 4;   // tx: 16 n-groups of 4; ty: 16 m-groups of 8
    const int row0 = blockIdx.x * 128;

    for (int i = tid; i < 256 * 64; i += 256) Es[i] = E[i];

    ull acc2[8][2];
    #pragma unroll
    for (int c = 0; c < 8; c++) { acc2[c][0] = 0ull; acc2[c][1] = 0ull; }

    for (int chunk = 0; chunk < 8; chunk++) {
        int k0 = chunk * 32;
        __syncthreads();           // protect Xs reuse (and orders Es fill on first pass)
        for (int i = tid; i < 4096; i += 256) {
            int rr = i >> 5, kk = i & 31;
            Xs[kk * 132 + rr] = X[(size_t)(row0 + rr) * 256 + k0 + kk];
        }
        __syncthreads();
        #pragma unroll
        for (int kk = 0; kk < 32; kk++) {
            float4 a0 = *(const float4*)&Xs[kk * 132 + ty * 8];
            float4 a1 = *(const float4*)&Xs[kk * 132 + ty * 8 + 4];
            ulonglong2 bq = *(const ulonglong2*)&Es[(k0 + kk) * 64 + tx * 4];
            ull ad[8] = {packdup(a0.x), packdup(a0.y), packdup(a0.z), packdup(a0.w),
                         packdup(a1.x), packdup(a1.y), packdup(a1.z), packdup(a1.w)};
            #pragma unroll
            for (int c = 0; c < 8; c++) {
                acc2[c][0] = fma2(ad[c], bq.x, acc2[c][0]);
                acc2[c][1] = fma2(ad[c], bq.y, acc2[c][1]);
            }
        }
    }
    // store into cell-major layout: F[(b*256+o)*16 + l][e]
    #pragma unroll
    for (int c = 0; c < 8; c++) {
        int row = row0 + ty * 8 + c;               // (b*L + l)*O + o
        int b = row >> 12;
        int l = (row >> 8) & 15;
        int o = row & 255;
        size_t fi = ((size_t)((b << 8) | o) * 16 + l) * 64 + tx * 4;
        float v0, v1, v2, v3;
        unpack2(acc2[c][0], v0, v1);
        unpack2(acc2[c][1], v2, v3);
        *(float4*)&g_F[fi] = make_float4(v0, v1, v2, v3);
    }
}

// ---------------- fused input-GEMM + LSTM (persistent per 64 cells) ---------
// SMEM: Ws[128][256] (Wi_flow|Wh transposed+gate-permuted) + As[128][72]
//       As rows 0..63 = F(l) (k-major per cell), rows 64..127 = h (dm-major per cell)
// F(l+1) is prefetched into registers BEFORE the GEMM so its global latency is
// hidden behind FFMA2 issue, then committed to SMEM post-barrier.
// Gate bias is register-resident across all 16 steps.
#define AS_STR  72
#define LSTM_SMEM ((32768 + 128 * AS_STR) * 4)
__global__ void __launch_bounds__(256, 1) lstm_kernel()
{
    extern __shared__ float sm[];
    float* Ws = sm;                 // 32768
    float* As = sm + 32768;         // 128*72
    const int tid = threadIdx.x;
    const int tx = tid & 31, ty = tid >> 5;       // tx: n-quads (dm=tx & dm=tx+32); ty: 8 cell-groups
    const int cellbase = blockIdx.x * 64;
    const int obase = cellbase & 255;

    for (int i = tid; i < 32768; i += 256) Ws[i] = g_Wpre[i];
    for (int i = tid; i < 64 * AS_STR; i += 256) As[64 * AS_STR + i] = 0.0f;   // h = 0
    for (int i = tid; i < 4096; i += 256) {                                    // stage F(0)
        int cc = i >> 6, e = i & 63;
        As[e * AS_STR + cc] = g_F[((size_t)(cellbase + cc) * 16 + 0) * 64 + e];
    }

    // gate bias: load once, keep in registers for all 16 steps
    ull bias2[8][4];
    #pragma unroll
    for (int c = 0; c < 8; c++) {
        const float* gb = &g_GbiasP[(obase + ty * 8 + c) * 256];
        float4 b0 = *(const float4*)&gb[tx * 4];
        float4 b1 = *(const float4*)&gb[128 + tx * 4];
        bias2[c][0] = pack2(b0.x, b0.y);
        bias2[c][1] = pack2(b0.z, b0.w);
        bias2[c][2] = pack2(b1.x, b1.y);
        bias2[c][3] = pack2(b1.z, b1.w);
    }
    __syncthreads();

    float cs[16];
    #pragma unroll
    for (int i = 0; i < 16; i++) cs[i] = 0.0f;
    float ssum0 = 0.0f, ssum1 = 0.0f, ssq0 = 0.0f, ssq1 = 0.0f;

    for (int l = 0; l < 16; l++) {
        // ---- prefetch F(l+1) into registers (hidden behind the GEMM) ----
        float fbuf[16];
        if (l < 15) {
            #pragma unroll
            for (int j = 0; j < 16; j++) {
                int i = tid + j * 256;
                int cc = i >> 6, e = i & 63;
                fbuf[j] = g_F[((size_t)(cellbase + cc) * 16 + (l + 1)) * 64 + e];
            }
        }

        // ---- acc init from register-resident gate bias ----
        ull acc2[8][4];
        #pragma unroll
        for (int c = 0; c < 8; c++)
            #pragma unroll
            for (int j = 0; j < 4; j++) acc2[c][j] = bias2[c][j];

        // ---- 64x256x128 GEMM: z = [F(l)|h] @ [Wi_flow|Wh]^T (gate-permuted, f32x2) ----
        #pragma unroll 4
        for (int k = 0; k < 128; k++) {
            float4 a0 = *(const float4*)&As[k * AS_STR + ty * 8];
            float4 a1 = *(const float4*)&As[k * AS_STR + ty * 8 + 4];
            ulonglong2 w0 = *(const ulonglong2*)&Ws[k * 256 + tx * 4];
            ulonglong2 w1 = *(const ulonglong2*)&Ws[k * 256 + 128 + tx * 4];
            ull ad[8] = {packdup(a0.x), packdup(a0.y), packdup(a0.z), packdup(a0.w),
                         packdup(a1.x), packdup(a1.y), packdup(a1.z), packdup(a1.w)};
            #pragma unroll
            for (int c = 0; c < 8; c++) {
                acc2[c][0] = fma2(ad[c], w0.x, acc2[c][0]);
                acc2[c][1] = fma2(ad[c], w0.y, acc2[c][1]);
                acc2[c][2] = fma2(ad[c], w1.x, acc2[c][2]);
                acc2[c][3] = fma2(ad[c], w1.y, acc2[c][3]);
            }
        }
        __syncthreads();   // all GEMM reads of As done

        // ---- gates + h writeback + F(l+1) commit ----
        #pragma unroll
        for (int c = 0; c < 8; c++) {
            #pragma unroll
            for (int hf = 0; hf < 2; hf++) {
                float zi, zf, zg, zo;
                unpack2(acc2[c][hf * 2 + 0], zi, zf);
                unpack2(acc2[c][hf * 2 + 1], zg, zo);
                float ig  = sigm_(zi);
                float fgt = sigm_(zf);
                float gg  = tanh_(zg);
                float og  = sigm_(zo);
                float cn = fmaf(fgt, cs[hf * 8 + c], ig * gg);
                cs[hf * 8 + c] = cn;
                float h = og * tanh_(cn);
                int dm = tx + hf * 32;
                As[(64 + dm) * AS_STR + ty * 8 + c] = h;
                if (hf == 0) { ssum0 += h; ssq0 = fmaf(h, h, ssq0); }
                else         { ssum1 += h; ssq1 = fmaf(h, h, ssq1); }
                if (l == 15)
                    g_hlast[(size_t)(cellbase + ty * 8 + c) * 64 + dm] = h;
            }
        }
        if (l < 15) {
            #pragma unroll
            for (int j = 0; j < 16; j++) {
                int i = tid + j * 256;
                int cc = i >> 6, e = i & 63;
                As[e * AS_STR + cc] = fbuf[j];
            }
        }
        __syncthreads();   // writes visible to next step's GEMM
    }

    // deterministic LN partials: [dm][ty] sums at 0..511, sumsq at 512..1023
    As[tx * 8 + ty]               = ssum0;
    As[(tx + 32) * 8 + ty]        = ssum1;
    As[512 + tx * 8 + ty]         = ssq0;
    As[512 + (tx + 32) * 8 + ty]  = ssq1;
    __syncthreads();
    if (tid < 128) {
        int base = (tid < 64) ? (tid * 8) : (512 + (tid - 64) * 8);
        float s = 0.0f;
        #pragma unroll
        for (int j = 0; j < 8; j++) s += As[base + j];
        g_part[blockIdx.x * 128 + tid] = s;
    }
}

// ---------------- LN stats finalize -----------------------------------------
__global__ void stats_kernel()
{
    int d = threadIdx.x;   // 64 threads
    float s = 0.0f, q = 0.0f;
    for (int c = 0; c < 128; c++) {
        s += g_part[c * 128 + d];
        q += g_part[c * 128 + 64 + d];
    }
    const float N = 131072.0f;
    float mean = s / N;
    float var  = q / N - mean * mean;
    g_mean[d] = mean;
    g_rstd[d] = rsqrtf(var + 1e-5f);
}

// ---------------- v = LN(h_last), lv = v @ Wl^T + bl ------------------------
__global__ void vlv_kernel(const float* __restrict__ gamma, const float* __restrict__ beta,
                           const float* __restrict__ Wl,    const float* __restrict__ bl)
{
    __shared__ float WlT[64 * 65];
    __shared__ float vs[4 * 64];
    int tid = threadIdx.x;
    for (int i = tid; i < 4096; i += 256) {
        int j = i >> 6, e = i & 63;
        WlT[e * 65 + j] = Wl[i];           // Wl[j][e]
    }
    int cl = tid >> 6, e0 = tid & 63;
    int cell = blockIdx.x * 4 + cl;
    float h = g_hlast[(size_t)cell * 64 + e0];
    float v = fmaf((h - g_mean[e0]) * g_rstd[e0], gamma[e0], beta[e0]);
    g_v[(size_t)cell * 64 + e0] = v;
    vs[cl * 64 + e0] = v;
    __syncthreads();
    int j = e0;
    float acc = bl[j];
    #pragma unroll
    for (int e = 0; e < 64; e++) acc = fmaf(vs[cl * 64 + e], WlT[e * 65 + j], acc);
    g_lv[(size_t)cell * 64 + j] = acc;
}

// ---------------- out[b,o,d] = sum_e lv[b,o,e]*v[b,d,e] ---------------------
// grid 512 = 32 b * 4 o-tiles * 4 d-tiles; 64x64 tile per block
__global__ void out_kernel(float* __restrict__ out)
{
    __shared__ float As2[64 * 68];
    __shared__ float Bs2[64 * 68];
    int bid = blockIdx.x;
    int b = bid >> 4, ot = (bid >> 2) & 3, dt = bid & 3;
    int tid = threadIdx.x;
    for (int i = tid; i < 4096; i += 256) {
        int r = i >> 6, e = i & 63;
        As2[e * 68 + r] = g_lv[((size_t)(b * 256 + ot * 64 + r)) * 64 + e];
        Bs2[e * 68 + r] = g_v [((size_t)(b * 256 + dt * 64 + r)) * 64 + e];
    }
    __syncthreads();
    int tx = tid & 15, ty = tid >> 4;
    int o0 = ty * 4, d0 = tx * 4;
    float acc[4][4];
    #pragma unroll
    for (int i = 0; i < 4; i++)
        #pragma unroll
        for (int j = 0; j < 4; j++) acc[i][j] = 0.0f;
    #pragma unroll 8
    for (int e = 0; e < 64; e++) {
        float4 a = *(const float4*)&As2[e * 68 + o0];
        float4 q = *(const float4*)&Bs2[e * 68 + d0];
        float av[4] = {a.x, a.y, a.z, a.w};
        float qv[4] = {q.x, q.y, q.z, q.w};
        #pragma unroll
        for (int i = 0; i < 4; i++)
            #pragma unroll
            for (int j = 0; j < 4; j++)
                acc[i][j] = fmaf(av[i], qv[j], acc[i][j]);
    }
    #pragma unroll
    for (int i = 0; i < 4; i++) {
        size_t oi = ((size_t)(b * 256 + ot * 64 + o0 + i)) * 256 + dt * 64 + d0;
        *(float4*)&out[oi] = make_float4(acc[i][0], acc[i][1], acc[i][2], acc[i][3]);
    }
}

// ---------------- launch -----------------------------------------------------
extern "C" void kernel_launch(void* const* d_in, const int* in_sizes, int n_in,
                              void* d_out, int out_size)
{
    const float* X     = (const float*)d_in[0];
    const float* dis   = (const float*)d_in[1];
    const float* E     = (const float*)d_in[2];
    const float* Wi    = (const float*)d_in[3];
    const float* Wh    = (const float*)d_in[4];
    const float* bi    = (const float*)d_in[5];
    const float* bh    = (const float*)d_in[6];
    const float* gamma = (const float*)d_in[7];
    const float* beta  = (const float*)d_in[8];
    const float* Wl    = (const float*)d_in[9];
    const float* bl    = (const float*)d_in[10];
    float* out = (float*)d_out;

    cudaFuncSetAttribute(gemm1_full, cudaFuncAttributeMaxDynamicSharedMemorySize, G1_SMEM);
    cudaFuncSetAttribute(lstm_kernel, cudaFuncAttributeMaxDynamicSharedMemorySize, LSTM_SMEM);

    prep_kernel<<<384, 256>>>(dis, E, Wi, Wh, bi, bh);
    gemm1_full<<<1024, 256, G1_SMEM>>>(X, E);
    lstm_kernel<<<128, 256, LSTM_SMEM>>>();
    stats_kernel<<<1, 64>>>();
    vlv_kernel<<<2048, 256>>>(gamma, beta, Wl, bl);
    out_kernel<<<512, 256>>>(out);
}